// round 9
// baseline (speedup 1.0000x reference)
#include <cuda_runtime.h>
#include <cuda_bf16.h>
#include <math.h>

#define NA 8400
#define BSZ 32
#define NM 32
#define NC 80
#define TOPK 9
#define NGT 8          // gts per k_pairs block
#define CAP2 32
#define AG 64          // anchors per k_assign block
#define FINF 3.402823e38f

// Zero-initialized at module load; k_assign re-zeroes after consuming, so the
// "all zeros at kernel_launch entry" invariant holds on every call/replay.
__device__ unsigned int g_maskpos[BSZ * NA];

// One block per (batch, gt-octet): 8 gts share every anchor load.
// Two-pass top-9 per (gt,level): pass1 = per-thread min(d2) over disjoint
// slices -> T = 9th extraction of the 256 minima (superset bound);
// pass2 = collect keys <= T via smem atomics; rank-select; IoU tail.
__global__ __launch_bounds__(256) void k_pairs(
    const float* __restrict__ anc,
    const float* __restrict__ gtb,
    const float* __restrict__ mask_gt)
{
    __shared__ float s_tmin[3][NGT][256];
    __shared__ float s_T[3][NGT];
    __shared__ int   s_cnt[3][NGT];
    __shared__ unsigned long long s_buf[3][NGT][CAP2];
    __shared__ int   s_cand[NGT][27];

    const int tid  = threadIdx.x;
    const int lane = tid & 31;
    const int w    = tid >> 5;              // warp id == gt-in-group later

    const int b   = blockIdx.x >> 2;
    const int grp = blockIdx.x & 3;
    const int g0  = grp * NGT;

    if (tid < 24) ((int*)s_cnt)[tid] = 0;

    // 8 gt centers in registers
    float gxs[NGT], gys[NGT];
    #pragma unroll
    for (int g = 0; g < NGT; ++g) {
        const float4 gt = ((const float4*)gtb)[b * NM + g0 + g];
        gxs[g] = (gt.x + gt.z) * 0.5f;
        gys[g] = (gt.y + gt.w) * 0.5f;
    }

    const int starts[3] = {0, 6400, 8000};
    const int lens[3]   = {6400, 1600, 400};

    // ---------------- Pass 1: per-thread minima ----------------
    for (int lvl = 0; lvl < 3; ++lvl) {
        const int start = starts[lvl], L = lens[lvl];
        float mn[NGT];
        #pragma unroll
        for (int g = 0; g < NGT; ++g) mn[g] = FINF;

        for (int base = 0; base < L; base += 1024) {
            float cax[4], cay[4];
            #pragma unroll
            for (int j = 0; j < 4; ++j) {
                const int al = base + j * 256 + tid;
                const int idx = start + (al < L ? al : L - 1);
                const float4 ab = ((const float4*)anc)[idx];
                float cx = (ab.x + ab.z) * 0.5f;
                const float cy = (ab.y + ab.w) * 0.5f;
                cx = (al < L) ? cx : 3.0e18f;   // sentinel -> d2 = inf
                cax[j] = cx; cay[j] = cy;
            }
            #pragma unroll
            for (int j = 0; j < 4; ++j) {
                #pragma unroll
                for (int g = 0; g < NGT; ++g) {
                    const float dx = gxs[g] - cax[j];
                    const float dy = gys[g] - cay[j];
                    const float d2 = fmaf(dx, dx, dy * dy);
                    mn[g] = fminf(mn[g], d2);
                }
            }
        }
        #pragma unroll
        for (int g = 0; g < NGT; ++g) s_tmin[lvl][g][tid] = mn[g];
    }
    __syncthreads();

    // ---------------- Threshold extraction: warp w -> gt w ----------------
    for (int lvl = 0; lvl < 3; ++lvl) {
        float v[8];
        #pragma unroll
        for (int j = 0; j < 8; ++j) v[j] = s_tmin[lvl][w][lane * 8 + j];
        float T = FINF;
        #pragma unroll
        for (int r = 0; r < TOPK; ++r) {
            float lm = v[0];
            #pragma unroll
            for (int j = 1; j < 8; ++j) lm = fminf(lm, v[j]);
            float m = lm;
            #pragma unroll
            for (int s = 16; s > 0; s >>= 1)
                m = fminf(m, __shfl_xor_sync(0xffffffffu, m, s));
            #pragma unroll
            for (int j = 0; j < 8; ++j) v[j] = (v[j] == m) ? FINF : v[j];
            T = m;
        }
        if (lane == 0) s_T[lvl][w] = T;
    }
    __syncthreads();

    // ---------------- Pass 2: collect keys <= T ----------------
    for (int lvl = 0; lvl < 3; ++lvl) {
        const int start = starts[lvl], L = lens[lvl];
        float Tl[NGT];
        #pragma unroll
        for (int g = 0; g < NGT; ++g) Tl[g] = s_T[lvl][g];

        for (int base = 0; base < L; base += 1024) {
            float cax[4], cay[4]; int ai[4];
            #pragma unroll
            for (int j = 0; j < 4; ++j) {
                const int al = base + j * 256 + tid;
                ai[j] = start + al;
                const int idx = start + (al < L ? al : L - 1);
                const float4 ab = ((const float4*)anc)[idx];
                float cx = (ab.x + ab.z) * 0.5f;
                const float cy = (ab.y + ab.w) * 0.5f;
                cx = (al < L) ? cx : 3.0e18f;
                cax[j] = cx; cay[j] = cy;
            }
            #pragma unroll
            for (int j = 0; j < 4; ++j) {
                #pragma unroll
                for (int g = 0; g < NGT; ++g) {
                    const float dx = gxs[g] - cax[j];
                    const float dy = gys[g] - cay[j];
                    const float d2 = fmaf(dx, dx, dy * dy);
                    if (d2 <= Tl[g]) {
                        const int pos = atomicAdd(&s_cnt[lvl][g], 1);
                        if (pos < CAP2)
                            s_buf[lvl][g][pos] =
                                ((unsigned long long)__float_as_uint(d2) << 32) |
                                (unsigned int)ai[j];
                    }
                }
            }
        }
    }
    __syncthreads();

    // ---------------- Rank-select + tail: warp w -> gt w ----------------
    const int p = b * NM + g0 + w;
    const float4 gt = ((const float4*)gtb)[p];
    const float mg = mask_gt[p];

    for (int lvl = 0; lvl < 3; ++lvl) {
        int C = s_cnt[lvl][w]; if (C > CAP2) C = CAP2;   // C >= 9 guaranteed
        if (lane < C) {
            const unsigned long long my = s_buf[lvl][w][lane];
            int rank = 0;
            for (int j = 0; j < C; ++j)
                rank += (s_buf[lvl][w][j] < my) ? 1 : 0;
            if (rank < TOPK)
                s_cand[w][lvl * TOPK + rank] = (int)(unsigned int)my;
        }
    }
    __syncwarp();

    // Candidate overlaps (_iou2d: unclipped areas, union eps 1e-6)
    float ov = 0.0f;
    int ca = 0;
    float4 ab = make_float4(0.f, 0.f, 0.f, 0.f);
    if (lane < 27) {
        ca = s_cand[w][lane];
        ab = ((const float4*)anc)[ca];
        const float area1 = (gt.z - gt.x) * (gt.w - gt.y);
        const float area2 = (ab.z - ab.x) * (ab.w - ab.y);
        const float ltx = fmaxf(gt.x, ab.x), lty = fmaxf(gt.y, ab.y);
        const float rbx = fminf(gt.z, ab.z), rby = fminf(gt.w, ab.w);
        const float ww = fmaxf(rbx - ltx, 0.0f), hh = fmaxf(rby - lty, 0.0f);
        const float o = ww * hh;
        ov = o / fmaxf(area1 + area2 - o, 1e-6f);
    }

    // mean + std(ddof=1) threshold via warp sums
    float s = (lane < 27) ? ov : 0.0f;
    #pragma unroll
    for (int sft = 16; sft > 0; sft >>= 1) s += __shfl_xor_sync(0xffffffffu, s, sft);
    const float mean = s * (1.0f / 27.0f);
    float dv = (lane < 27) ? (ov - mean) * (ov - mean) : 0.0f;
    #pragma unroll
    for (int sft = 16; sft > 0; sft >>= 1) dv += __shfl_xor_sync(0xffffffffu, dv, sft);
    const float thr = mean + sqrtf(dv * (1.0f / 26.0f));

    if (lane < 27 && ov > thr && mg > 0.0f) {
        const float ax = (ab.x + ab.z) * 0.5f;
        const float ay = (ab.y + ab.w) * 0.5f;
        const float mn2 = fminf(fminf(ax - gt.x, ay - gt.y),
                                fminf(gt.z - ax, gt.w - ay));
        if (mn2 > 1e-9f) atomicOr(&g_maskpos[b * NA + ca], 1u << (g0 + w));
    }
}

// One block per AG=64 anchors. Phase A (64 thr): assignment + small outputs
// (+ re-zero the gt bitmask). Phase B (256 thr): coalesced score-row writes.
__global__ __launch_bounds__(256) void k_assign(
    const float* __restrict__ anc,
    const int*   __restrict__ gt_labels,
    const float* __restrict__ gtb,
    const float* __restrict__ pd,
    float* __restrict__ o_lab,
    float* __restrict__ o_box,
    float* __restrict__ o_scr,
    float* __restrict__ o_fg)
{
    __shared__ int   s_lab[AG];
    __shared__ float s_scr[AG];

    const int base = blockIdx.x * AG;
    const int tid  = threadIdx.x;

    if (tid < AG) {
        const int idx = base + tid;
        const int b = idx / NA;
        const int a = idx - b * NA;

        const unsigned int m = g_maskpos[idx];
        g_maskpos[idx] = 0u;                 // restore invariant for next call
        const int cnt = __popc(m);
        int tgt = 0;
        const bool fg = (cnt > 0);

        if (cnt == 1) {
            tgt = __ffs(m) - 1;
        } else if (cnt > 1) {
            // argmax over gts of full overlaps (first-occurrence ties)
            const float4 ab = ((const float4*)anc)[a];
            const float area2 = (ab.z - ab.x) * (ab.w - ab.y);
            float best = -1.0f;
            for (int gg = 0; gg < NM; ++gg) {
                const float4 gb = ((const float4*)gtb)[b * NM + gg];
                const float area1 = (gb.z - gb.x) * (gb.w - gb.y);
                const float ltx = fmaxf(gb.x, ab.x), lty = fmaxf(gb.y, ab.y);
                const float rbx = fminf(gb.z, ab.z), rby = fminf(gb.w, ab.w);
                const float ww = fmaxf(rbx - ltx, 0.0f), hh = fmaxf(rby - lty, 0.0f);
                const float ovv = ww * hh;
                const float v = ovv / fmaxf(area1 + area2 - ovv, 1e-6f);
                if (v > best) { best = v; tgt = gg; }
            }
        }

        const int label = fg ? gt_labels[b * NM + tgt] : NC;
        const float4 tb = ((const float4*)gtb)[b * NM + tgt];

        o_lab[idx] = (float)label;
        ((float4*)o_box)[idx] = tb;
        o_fg[idx] = fg ? 1.0f : 0.0f;

        float score = 0.0f;
        if (fg) {
            // _iou_batched: clipped areas, +1e-9 in denominator
            const float4 pb = ((const float4*)pd)[(size_t)b * NA + a];
            const float iw = fmaxf(fminf(tb.z, pb.z) - fmaxf(tb.x, pb.x), 0.0f);
            const float ih = fmaxf(fminf(tb.w, pb.w) - fmaxf(tb.y, pb.y), 0.0f);
            const float ovv = iw * ih;
            const float a1 = fmaxf(tb.z - tb.x, 0.0f) * fmaxf(tb.w - tb.y, 0.0f);
            const float a2 = fmaxf(pb.z - pb.x, 0.0f) * fmaxf(pb.w - pb.y, 0.0f);
            score = ovv / (a1 + a2 - ovv + 1e-9f);
        }
        s_lab[tid] = fg ? label : -1;
        s_scr[tid] = score;
    }
    __syncthreads();

    // Phase B: 64 rows x 20 float4 = 1280 float4s, coalesced.
    float4* sc4 = (float4*)o_scr + (size_t)base * (NC / 4);
    #pragma unroll
    for (int it = 0; it < AG * (NC / 4) / 256; ++it) {
        const int j  = it * 256 + tid;
        const int an = j / (NC / 4);
        const int q  = j - an * (NC / 4);
        float4 v = make_float4(0.f, 0.f, 0.f, 0.f);
        const int l = s_lab[an];
        if (l >= 0 && (l >> 2) == q) {
            const float sc = s_scr[an];
            if ((l & 3) == 0) v.x = sc;
            else if ((l & 3) == 1) v.y = sc;
            else if ((l & 3) == 2) v.z = sc;
            else v.w = sc;
        }
        sc4[j] = v;
    }
}

extern "C" void kernel_launch(void* const* d_in, const int* in_sizes, int n_in,
                              void* d_out, int out_size)
{
    const float* anc = (const float*)d_in[0];   // [8400,4]
    const int*   gtl = (const int*)  d_in[1];   // [32,32,1]
    const float* gtb = (const float*)d_in[2];   // [32,32,4]
    const float* mgt = (const float*)d_in[3];   // [32,32,1]
    const float* pd  = (const float*)d_in[4];   // [32,8400,4]

    float* out   = (float*)d_out;
    float* o_lab = out;
    float* o_box = o_lab + (size_t)BSZ * NA;
    float* o_scr = o_box + (size_t)BSZ * NA * 4;
    float* o_fg  = o_scr + (size_t)BSZ * NA * NC;

    k_pairs<<<BSZ * (NM / NGT), 256>>>(anc, gtb, mgt);
    k_assign<<<BSZ * NA / AG, 256>>>(anc, gtl, gtb, pd,
                                     o_lab, o_box, o_scr, o_fg);
}